// round 5
// baseline (speedup 1.0000x reference)
#include <cuda_runtime.h>
#include <cuda_bf16.h>
#include <cstdint>

// Segment-sum scatter via TMA bulk-reduce.
//
// Per block (256 threads, 4 iterations): 256 edges.
//   - loads: R1-style coalesced thread-per-quad, 4 quads/thread front-batched
//   - stage: each iteration's 256 float4s -> 4KB smem region (4 regions, 16KB)
//   - reduce: lane (t&3)==0 of each edge issues ONE
//       cp.reduce.async.bulk.global.shared::cta.add.f32 of 64B
//     replacing 4x RED.E.ADD.F32.V4 -> 4x fewer reduction ops, same bytes.
//
// E = 3.2M edges exactly = 12500 blocks * 256 edges, no bounds checks.

#define E_TOTAL          3200000
#define TPB              256
#define ITERS            4
#define EDGES_PER_BLOCK  (TPB / 4 * ITERS)      // 256
#define NBLK             (E_TOTAL / EDGES_PER_BLOCK)  // 12500

__global__ void __launch_bounds__(TPB)
spmm_bulkred_kernel(const int* __restrict__ src,
                    const float4* __restrict__ w4,   // [E*4]
                    float* __restrict__ out)         // [N*16] f32
{
    __shared__ float4 stage[ITERS * TPB];            // 16 KB

    const int t = threadIdx.x;
    const int blockEdgeBase = blockIdx.x * EDGES_PER_BLOCK;
    const int blockQuadBase = blockIdx.x * (EDGES_PER_BLOCK * 4);

    // Front-batched loads: 4 independent coalesced LDG.128 + 4 src ints.
    float4 v[ITERS];
    int    s[ITERS];
#pragma unroll
    for (int i = 0; i < ITERS; i++) {
        v[i] = __ldcs(&w4[blockQuadBase + i * TPB + t]);   // streamed once
        s[i] = __ldg(&src[blockEdgeBase + i * (TPB / 4) + (t >> 2)]);
    }

    // Stage into smem: warp-contiguous 16B stores, conflict-free.
#pragma unroll
    for (int i = 0; i < ITERS; i++)
        stage[i * TPB + t] = v[i];

    __syncwarp();
    asm volatile("fence.proxy.async.shared::cta;" ::: "memory");

    uint32_t smem_base;
    asm("{ .reg .u64 a; cvta.to.shared.u64 a, %1; cvt.u32.u64 %0, a; }"
        : "=r"(smem_base) : "l"(stage));

    if ((t & 3) == 0) {
#pragma unroll
        for (int i = 0; i < ITERS; i++) {
            const float* dst = out + (size_t)s[i] * 16;         // 64B row, 64B-aligned
            uint32_t sa = smem_base + (uint32_t)(i * TPB + t) * 16u;
            asm volatile(
                "cp.reduce.async.bulk.global.shared::cta.bulk_group.add.f32 "
                "[%0], [%1], 64;"
                :: "l"(dst), "r"(sa)
                : "memory");
        }
    }
    // Ensure all bulk reduces complete before the kernel retires.
    asm volatile("cp.async.bulk.commit_group;" ::: "memory");
    asm volatile("cp.async.bulk.wait_group 0;" ::: "memory");
}

extern "C" void kernel_launch(void* const* d_in, const int* in_sizes, int n_in,
                              void* d_out, int out_size)
{
    const int*   edge   = (const int*)d_in[0];   // edge[0] = src, first E ints
    const float* edge_w = (const float*)d_in[1];

    // d_out poisoned to 0xAA -> zero it (memset node is graph-capturable).
    cudaMemsetAsync(d_out, 0, (size_t)out_size * sizeof(float), 0);

    spmm_bulkred_kernel<<<NBLK, TPB>>>(
        edge,
        (const float4*)edge_w,
        (float*)d_out);
}

// round 6
// speedup vs baseline: 1.0306x; 1.0306x over previous
#include <cuda_runtime.h>
#include <cuda_bf16.h>

// Segment-sum scatter, thread-per-quad, 2 quads/thread, 512-thread blocks.
//
// Model (R1 vs R3 invariance): bound by the L2-slice atomic RMW rate
// (~1.0-1.3 cyc per 16B RMW per slice, 12.8M ops / 184 slices). SM-side
// shape is not the bottleneck; this round confirms the floor while trimming
// per-thread LSU op count (1 src + 1 w + 1 RED per quad-slot x2) and
// register pressure for a maximal eligible-warp pool.
//
// Addressing (both batches): warp loads 32 consecutive float4s = 4 x 128B
// lines per LDG.128; 4 lanes share one broadcast src int; each edge's 4
// RED.E.ADD.F32.V4 lanes cover its contiguous 64B output row (1 line).
// w is streamed once -> __ldcs (evict-first) so the 6.4 MB output region
// (pre-warmed dirty in L2 by the memset) stays resident for the RMWs.
//
// Fixed sizes: E = 3,200,000 edges, F = 16 -> 12.8M quads.
// 6.4M threads x 2 quads, exact: 12500 blocks x 512 threads.

#define E_TOTAL   3200000
#define NUM_QUADS (E_TOTAL * 4)
#define TPB       512
#define QPT       2
#define TOTAL_THREADS (NUM_QUADS / QPT)        // 6,400,000
#define NBLK          (TOTAL_THREADS / TPB)    // 12,500

__global__ void __launch_bounds__(TPB)
spmm_scatter_kernel(const int* __restrict__ src,
                    const float4* __restrict__ w4,   // [E*4] float4
                    float4* __restrict__ out4)       // [N*4] float4
{
    const int tid = blockIdx.x * TPB + threadIdx.x;
    const int S   = TOTAL_THREADS;

    const int i0 = tid;
    const int i1 = tid + S;

    // Front-batched independent loads (MLP 4).
    int    s0 = __ldg(&src[i0 >> 2]);
    int    s1 = __ldg(&src[i1 >> 2]);
    float4 v0 = __ldcs(&w4[i0]);
    float4 v1 = __ldcs(&w4[i1]);

    atomicAdd(&out4[((size_t)s0 << 2) + (i0 & 3)], v0);
    atomicAdd(&out4[((size_t)s1 << 2) + (i1 & 3)], v1);
}

extern "C" void kernel_launch(void* const* d_in, const int* in_sizes, int n_in,
                              void* d_out, int out_size)
{
    const int*   edge   = (const int*)d_in[0];   // edge[0] = src, first E ints
    const float* edge_w = (const float*)d_in[1];

    // d_out poisoned to 0xAA -> zero it (memset node is graph-capturable);
    // this also pre-warms the 6.4 MB destination region dirty in L2.
    cudaMemsetAsync(d_out, 0, (size_t)out_size * sizeof(float), 0);

    spmm_scatter_kernel<<<NBLK, TPB>>>(
        edge,
        (const float4*)edge_w,
        (float4*)d_out);
}

// round 7
// speedup vs baseline: 1.4343x; 1.3917x over previous
#include <cuda_runtime.h>
#include <cuda_bf16.h>

// Segment-sum scatter at the REDG throughput floor.
//
// Model: per-SM RED.E.ADD.F32.V4 issue rate (~1.05 cyc/op/SM, between the
// measured 0.854/1.29 cyc/lane REDG rates) binds at ~50.5us for 12.8M REDs
// over 148 SMs. Op count is irreducible (16B max RED width, payload fixed,
// bf16 fails the 1e-3 budget, dedup has ~0 expected hits on random indices).
//
// Proven-optimal shape (R1/R3 both hit 50.5us; TPB=512 and TMA variants both
// regressed to ~70us): TPB=256, 4 quads/thread grid-strided by the total
// thread count. Warp loads 32 consecutive float4s = 4 x 128B lines per
// LDG.128; 4 lanes share one broadcast src int; 8 loads front-batched
// (MLP_p1=8) ahead of 4 fire-and-forget REDs. edge_w streams once (__ldcs,
// evict-first) so the 6.4 MB output region stays L2-resident for the RMWs.
//
// Fixed sizes: E = 3,200,000, F = 16 -> 12.8M quads = 3.2M threads x 4.

#define E_TOTAL   3200000
#define NUM_QUADS (E_TOTAL * 4)
#define TPB       256
#define QPT       4
#define TOTAL_THREADS (NUM_QUADS / QPT)        // 3,200,000
#define NBLK          (TOTAL_THREADS / TPB)    // 12,500

__global__ void __launch_bounds__(TPB)
spmm_scatter_kernel(const int* __restrict__ src,
                    const float4* __restrict__ w4,   // [E*4] float4
                    float4* __restrict__ out4)       // [N*4] float4
{
    const int tid = blockIdx.x * TPB + threadIdx.x;
    const int S   = TOTAL_THREADS;

    const int i0 = tid;
    const int i1 = tid + S;
    const int i2 = tid + 2 * S;
    const int i3 = tid + 3 * S;

    // Front-batched independent loads (ptxas hoists these together, MLP ~8).
    int s0 = __ldg(&src[i0 >> 2]);
    int s1 = __ldg(&src[i1 >> 2]);
    int s2 = __ldg(&src[i2 >> 2]);
    int s3 = __ldg(&src[i3 >> 2]);

    float4 v0 = __ldcs(&w4[i0]);   // evict-first: edge_w streams once,
    float4 v1 = __ldcs(&w4[i1]);   // keep L2 for the atomic destinations
    float4 v2 = __ldcs(&w4[i2]);
    float4 v3 = __ldcs(&w4[i3]);

    atomicAdd(&out4[((size_t)s0 << 2) + (i0 & 3)], v0);
    atomicAdd(&out4[((size_t)s1 << 2) + (i1 & 3)], v1);
    atomicAdd(&out4[((size_t)s2 << 2) + (i2 & 3)], v2);
    atomicAdd(&out4[((size_t)s3 << 2) + (i3 & 3)], v3);
}

extern "C" void kernel_launch(void* const* d_in, const int* in_sizes, int n_in,
                              void* d_out, int out_size)
{
    const int*   edge   = (const int*)d_in[0];   // edge[0] = src, first E ints
    const float* edge_w = (const float*)d_in[1];

    // d_out poisoned to 0xAA -> zero it (memset node is graph-capturable);
    // also pre-warms the 6.4 MB destination region in L2.
    cudaMemsetAsync(d_out, 0, (size_t)out_size * sizeof(float), 0);

    spmm_scatter_kernel<<<NBLK, TPB>>>(
        edge,
        (const float4*)edge_w,
        (float4*)d_out);
}